// round 4
// baseline (speedup 1.0000x reference)
#include <cuda_runtime.h>

// RegL1Loss: out[b] = sum_{p,d} valid * |preds[b, idx] - val| / num_people[b]
// B=32, P=64, D=34, L=1048576. gts packed as [...,3] = (val, idx_as_float, flag).
//
// Layout trick: PD = 2176 = 544 * 4. One CTA per batch, 544 threads (17 warps),
// each thread owns exactly 4 elements = 12 consecutive floats = 3 float4 loads
// (16B-aligned since 12*4*t = 48t bytes). All loads + all 4 gathers are
// independent -> latency chain depth is 2 memory round-trips total.

#define B 32
#define P 64
#define D 34
#define PD (P * D)        // 2176
#define L 1048576
#define NT 544            // 17 warps
#define NW (NT / 32)      // 17

__global__ __launch_bounds__(NT) void regl1_kernel(
    const float* __restrict__ preds,
    const float* __restrict__ gts,
    float* __restrict__ out)
{
    const int b   = blockIdx.x;
    const int tid = threadIdx.x;

    __shared__ int   person_valid[P];
    __shared__ float warp_sums[NW];

    if (tid < P) person_valid[tid] = 0;
    __syncthreads();

    const float4* __restrict__ g4 =
        (const float4*)(gts + (size_t)b * PD * 3) + (size_t)tid * 3;
    const float* __restrict__ pr = preds + (size_t)b * L;

    // 3 coalesced vector loads: 12 floats = 4 (val, idx, flag) triples.
    float4 a0 = g4[0];
    float4 a1 = g4[1];
    float4 a2 = g4[2];

    float vals[4] = { a0.x, a0.w, a1.z, a2.y };
    float fidx[4] = { a0.y, a1.x, a1.w, a2.z };
    float flag[4] = { a0.z, a1.y, a2.x, a2.w };

    bool v[4];
    float gat[4];
    #pragma unroll
    for (int i = 0; i < 4; i++) {
        v[i] = flag[i] > 0.0f;
        // predicated independent gathers — all 4 in flight at once
        gat[i] = v[i] ? __ldg(pr + (int)fidx[i]) : 0.0f;
    }

    const int e0 = tid * 4;
    float acc = 0.0f;
    #pragma unroll
    for (int i = 0; i < 4; i++) {
        if (v[i]) {
            acc += fabsf(gat[i] - vals[i]);
            person_valid[(e0 + i) / D] = 1;   // benign race: all writers store 1
        }
    }

    // warp reduce
    #pragma unroll
    for (int off = 16; off > 0; off >>= 1)
        acc += __shfl_xor_sync(0xFFFFFFFFu, acc, off);

    const int wid = tid >> 5;
    const int lid = tid & 31;
    if (lid == 0) warp_sums[wid] = acc;
    __syncthreads();

    if (wid == 0) {
        float total = (lid < NW) ? warp_sums[lid] : 0.0f;
        #pragma unroll
        for (int off = 16; off > 0; off >>= 1)
            total += __shfl_xor_sync(0xFFFFFFFFu, total, off);

        int cnt = person_valid[lid] + person_valid[lid + 32];
        #pragma unroll
        for (int off = 16; off > 0; off >>= 1)
            cnt += __shfl_xor_sync(0xFFFFFFFFu, cnt, off);

        if (lid == 0)
            out[b] = total / (float)cnt;
    }
}

extern "C" void kernel_launch(void* const* d_in, const int* in_sizes, int n_in,
                              void* d_out, int out_size)
{
    const float* preds = (const float*)d_in[0];
    const float* gts   = (const float*)d_in[1];
    float* out = (float*)d_out;
    regl1_kernel<<<B, NT>>>(preds, gts, out);
}